// round 12
// baseline (speedup 1.0000x reference)
#include <cuda_runtime.h>
#include <cstdint>

// CostVolume: out[b,d,h,x] = (1/128) * sum_c L[b,c,h,x]*R[b,c,h,x-d], x>=d else 0
// B=8 C=128 H=128 W=240 V=48
// Tile XT=8/IT=12 (byte-optimal at 96 acc regs): 4 warps, warp w owns
// d in [12w,12w+12), lane<30 owns x in [8*lane, 8*lane+8).
// Parity-phased pairing: even/odd d share the same aligned R pairs.
// XOR-swizzled smem rows (32B lane stride conflict-free); division-free
// cp.async loader; 2-stage register double-buffering of operands.
#define B_  8
#define C_  128
#define H_  128
#define W_  240
#define V_  48
#define HW_ (H_*W_)

#define CC      16            // channels per chunk
#define NCH     (C_/CC)       // 8 chunks
#define THREADS 128
#define RPITCH  1152          // R row: (48 pad + 240 data) * 4 B
#define LPITCH  1024          // L row: 240*4 + 64 B zero pad
#define RPADB   192           // R left pad bytes

typedef unsigned long long ull;

// XOR 128B-block bits into 16B-unit bits (row-local). Involution; applied on
// both store and load. Row pitches are multiples of 128 B so the within-row
// bank pattern is preserved across rows.
__device__ __forceinline__ uint32_t sw(uint32_t c) { return c ^ ((c >> 3) & 0x70); }

__device__ __forceinline__ ull pk(float lo, float hi) {
    ull r; asm("mov.b64 %0, {%1, %2};" : "=l"(r) : "f"(lo), "f"(hi)); return r;
}
__device__ __forceinline__ void upk(ull v, float& lo, float& hi) {
    asm("mov.b64 {%0, %1}, %2;" : "=f"(lo), "=f"(hi) : "l"(v));
}
__device__ __forceinline__ void fma2(ull& acc, ull a, ull b) {
    asm("fma.rn.f32x2 %0, %1, %2, %0;" : "+l"(acc) : "l"(a), "l"(b));
}
__device__ __forceinline__ void cpasync16(uint32_t saddr, const void* g) {
    asm volatile("cp.async.cg.shared.global [%0], [%1], 16;" :: "r"(saddr), "l"(g));
}

struct Stage {
    float4 Lq0, Lq1; float Ls;
    float4 R0, R1, R2, R3, R4;
};

__global__ void __launch_bounds__(THREADS, 3)
cv_kernel(const float* __restrict__ L, const float* __restrict__ R,
          float* __restrict__ out)
{
    extern __shared__ char smem[];
    char* const smR = smem;                       // [2][CC][RPITCH]
    char* const smL = smem + 2 * CC * RPITCH;     // [2][CC][LPITCH]

    const int tid  = threadIdx.x;
    const int lane = tid & 31;
    const int w    = tid >> 5;                    // 0..3
    const int h = blockIdx.x, b = blockIdx.y;

    const int i0 = w * 12;                        // disparity base
    const int xb = lane * 8;                      // x base
    const bool act  = (lane < 30);
    const bool edge = (lane < 29);                // x=xb+8 valid

    const float* Lbase = L + ((size_t)b * C_ * H_ + h) * W_;
    const float* Rbase = R + ((size_t)b * C_ * H_ + h) * W_;

    // --- one-time pad zeroing ---
    // R rows bytes [0,192): closed under sw() (blocks 0-1), zero directly.
    for (int i = tid; i < 2 * CC * 48; i += THREADS) {
        int row = i / 48, k = i - row * 48;
        *(float*)(smR + row * RPITCH + k * 4) = 0.0f;
    }
    // L rows bytes [960,1024): zero through sw().
    for (int i = tid; i < 2 * CC * 16; i += THREADS) {
        int row = i / 16, k = i - row * 16;
        *(float*)(smL + row * LPITCH + sw(960 + k * 4)) = 0.0f;
    }

    // --- division-free loader: thread<120 owns (row0=t>=60, col=t%60);
    // covers rows row0+2k, k<8, for both L and R tiles (16 cp.async/chunk).
    const bool loader = (tid < 120);
    const int lr0  = (tid >= 60) ? 1 : 0;
    const int lcol = tid - lr0 * 60;              // quad index 0..59
    const float* gL = Lbase + (size_t)lr0 * HW_ + lcol * 4;
    const float* gR = Rbase + (size_t)lr0 * HW_ + lcol * 4;
    const uint32_t sLb = (uint32_t)__cvta_generic_to_shared(smL)
                       + (uint32_t)lr0 * LPITCH + sw((uint32_t)lcol * 16);
    const uint32_t sRb = (uint32_t)__cvta_generic_to_shared(smR)
                       + (uint32_t)lr0 * RPITCH + sw(RPADB + (uint32_t)lcol * 16);

    auto issue_load = [&](int buf) {
        if (loader) {
            const uint32_t dL = sLb + (uint32_t)buf * (CC * LPITCH);
            const uint32_t dR = sRb + (uint32_t)buf * (CC * RPITCH);
            #pragma unroll
            for (int k = 0; k < 8; k++) {         // rows lr0 + 2k
                cpasync16(dL + k * (2 * LPITCH), gL + (size_t)k * 2 * HW_);
                cpasync16(dR + k * (2 * RPITCH), gR + (size_t)k * 2 * HW_);
            }
        }
        asm volatile("cp.async.commit_group;");
    };

    // accE[j][t]: d=i0+2j,  x pair (xb+2t,   xb+2t+1)
    // accO[j][t]: d=i0+2j+1, x pair (xb+2t+1, xb+2t+2)
    // Both consume R pair P[t-j+6].
    ull accE[6][4], accO[6][4];
    #pragma unroll
    for (int j = 0; j < 6; j++)
        #pragma unroll
        for (int t = 0; t < 4; t++) { accE[j][t] = 0ull; accO[j][t] = 0ull; }

    // Swizzled row-local byte offsets (constant for whole kernel).
    // R window floats [xb-i0-12, xb-i0+8) at padded col 36+xb-i0 (16B aligned).
    const uint32_t rbb = (uint32_t)(4 * (36 + xb - i0));
    const uint32_t rQ0 = sw(rbb),      rQ1 = sw(rbb + 16), rQ2 = sw(rbb + 32);
    const uint32_t rQ3 = sw(rbb + 48), rQ4 = sw(rbb + 64);
    const uint32_t lQ0 = sw((uint32_t)xb * 4);
    const uint32_t lQ1 = sw((uint32_t)xb * 4 + 16);
    const uint32_t lS  = sw((uint32_t)xb * 4 + 32);   // L[xb+8] (pad-safe)

    issue_load(0);
    gL += CC * HW_; gR += CC * HW_;

    #pragma unroll 1
    for (int ch = 0; ch < NCH; ch++) {
        const int buf = ch & 1;
        if (ch + 1 < NCH) {
            issue_load((ch + 1) & 1);
            gL += CC * HW_; gR += CC * HW_;
            asm volatile("cp.async.wait_group 1;");
        } else {
            asm volatile("cp.async.wait_group 0;");
        }
        __syncthreads();

        if (act) {
            const char* rrow = smR + buf * (CC * RPITCH);
            const char* lrow = smL + buf * (CC * LPITCH);
            Stage SA, SB;

            #define LDS_STAGE(S, cc) do {                                    \
                (S).Lq0 = *(const float4*)(lrow + (cc) * LPITCH + lQ0);      \
                (S).Lq1 = *(const float4*)(lrow + (cc) * LPITCH + lQ1);      \
                (S).Ls  = *(const float*) (lrow + (cc) * LPITCH + lS);       \
                (S).R0  = *(const float4*)(rrow + (cc) * RPITCH + rQ0);      \
                (S).R1  = *(const float4*)(rrow + (cc) * RPITCH + rQ1);      \
                (S).R2  = *(const float4*)(rrow + (cc) * RPITCH + rQ2);      \
                (S).R3  = *(const float4*)(rrow + (cc) * RPITCH + rQ3);      \
                (S).R4  = *(const float4*)(rrow + (cc) * RPITCH + rQ4);      \
            } while (0)

            #define FMA_STAGE(S) do {                                        \
                ull Le0 = pk((S).Lq0.x, (S).Lq0.y);   /* aligned: elided */  \
                ull Le1 = pk((S).Lq0.z, (S).Lq0.w);                          \
                ull Le2 = pk((S).Lq1.x, (S).Lq1.y);                          \
                ull Le3 = pk((S).Lq1.z, (S).Lq1.w);                          \
                ull Lo0 = pk((S).Lq0.y, (S).Lq0.z);   /* 8 MOVs total */     \
                ull Lo1 = pk((S).Lq0.w, (S).Lq1.x);                          \
                ull Lo2 = pk((S).Lq1.y, (S).Lq1.z);                          \
                ull Lo3 = pk((S).Lq1.w, (S).Ls);                             \
                ull P[10];                            /* all aligned halves */\
                P[0] = pk((S).R0.x, (S).R0.y); P[1] = pk((S).R0.z, (S).R0.w);\
                P[2] = pk((S).R1.x, (S).R1.y); P[3] = pk((S).R1.z, (S).R1.w);\
                P[4] = pk((S).R2.x, (S).R2.y); P[5] = pk((S).R2.z, (S).R2.w);\
                P[6] = pk((S).R3.x, (S).R3.y); P[7] = pk((S).R3.z, (S).R3.w);\
                P[8] = pk((S).R4.x, (S).R4.y); P[9] = pk((S).R4.z, (S).R4.w);\
                _Pragma("unroll")                                            \
                for (int j = 0; j < 6; j++) {                                \
                    fma2(accE[j][0], Le0, P[6 - j]);                         \
                    fma2(accO[j][0], Lo0, P[6 - j]);                         \
                    fma2(accE[j][1], Le1, P[7 - j]);                         \
                    fma2(accO[j][1], Lo1, P[7 - j]);                         \
                    fma2(accE[j][2], Le2, P[8 - j]);                         \
                    fma2(accO[j][2], Lo2, P[8 - j]);                         \
                    fma2(accE[j][3], Le3, P[9 - j]);                         \
                    fma2(accO[j][3], Lo3, P[9 - j]);                         \
                }                                                            \
            } while (0)

            LDS_STAGE(SA, 0);
            #pragma unroll
            for (int cc = 0; cc < CC; cc += 2) {
                if (cc + 1 < CC) LDS_STAGE(SB, cc + 1);
                FMA_STAGE(SA);
                if (cc + 2 < CC) LDS_STAGE(SA, cc + 2);
                if (cc + 1 < CC) FMA_STAGE(SB);
            }
            #undef LDS_STAGE
            #undef FMA_STAGE
        }
        __syncthreads();
    }

    const float s = 1.0f / 128.0f;
    if (act) {
        #pragma unroll
        for (int j = 0; j < 6; j++) {
            // even d: aligned x in [xb, xb+8)
            const int de = i0 + 2 * j;
            float e0,e1,e2,e3,e4,e5,e6,e7;
            upk(accE[j][0], e0, e1);
            upk(accE[j][1], e2, e3);
            upk(accE[j][2], e4, e5);
            upk(accE[j][3], e6, e7);
            float* oe = out + (((size_t)b * V_ + de) * H_ + h) * W_ + xb;
            float4 o0, o1;
            o0.x=e0*s; o0.y=e1*s; o0.z=e2*s; o0.w=e3*s;
            o1.x=e4*s; o1.y=e5*s; o1.z=e6*s; o1.w=e7*s;
            *(float4*)(oe)     = o0;
            *(float4*)(oe + 4) = o1;

            // odd d: x in [xb+1, xb+8]
            float q0,q1,q2,q3,q4,q5,q6,q7;
            upk(accO[j][0], q0, q1);
            upk(accO[j][1], q2, q3);
            upk(accO[j][2], q4, q5);
            upk(accO[j][3], q6, q7);
            float* oo = out + (((size_t)b * V_ + de + 1) * H_ + h) * W_ + xb;
            oo[1] = q0*s; oo[2] = q1*s; oo[3] = q2*s; oo[4] = q3*s;
            oo[5] = q4*s; oo[6] = q5*s; oo[7] = q6*s;
            if (edge) oo[8] = q7*s;      // lane 29 skips x=240
        }
    } else if (lane == 30) {
        // out[x=0, odd d]: never produced by the odd pipeline; 0 since x<d.
        #pragma unroll
        for (int j = 0; j < 6; j++) {
            const int d = i0 + 2 * j + 1;
            out[(((size_t)b * V_ + d) * H_ + h) * W_] = 0.0f;
        }
    }
}

extern "C" void kernel_launch(void* const* d_in, const int* in_sizes, int n_in,
                              void* d_out, int out_size)
{
    const float* L = (const float*)d_in[0];
    const float* R = (const float*)d_in[1];
    float* out = (float*)d_out;

    const int smem_bytes = 2 * CC * RPITCH + 2 * CC * LPITCH;  // 69632
    cudaFuncSetAttribute(cv_kernel, cudaFuncAttributeMaxDynamicSharedMemorySize,
                         smem_bytes);
    cv_kernel<<<dim3(H_, B_), THREADS, smem_bytes>>>(L, R, out);
}

// round 13
// speedup vs baseline: 1.0515x; 1.0515x over previous
#include <cuda_runtime.h>
#include <cstdint>

// CostVolume: out[b,d,h,x] = (1/128) * sum_c L[b,c,h,x]*R[b,c,h,x-d], x>=d else 0
// B=8 C=128 H=128 W=240 V=48
// R11 inner loop (XT=4, IT=24, parity-phased pairing, 2-stage operand
// double-buffering) on a finer grid: each CTA = 64 threads (2 warps) handling
// a 120-wide x tile of one (b,h) row. grid = 128 x 8 x 2. 6 CTAs/SM.
#define B_  8
#define C_  128
#define H_  128
#define W_  240
#define V_  48
#define HW_ (H_*W_)

#define CC   16            // channels per chunk
#define NCH  (C_/CC)       // 8 chunks
#define THREADS 64
#define XW   120           // x width per CTA
#define RW2  168           // R tile row floats: 48 halo/pad + 120
#define LW   124           // L tile row floats: 120 + 4 edge

typedef unsigned long long ull;

__device__ __forceinline__ ull pk(float lo, float hi) {
    ull r; asm("mov.b64 %0, {%1, %2};" : "=l"(r) : "f"(lo), "f"(hi)); return r;
}
__device__ __forceinline__ void upk(ull v, float& lo, float& hi) {
    asm("mov.b64 {%0, %1}, %2;" : "=f"(lo), "=f"(hi) : "l"(v));
}
__device__ __forceinline__ void fma2(ull& acc, ull a, ull b) {
    asm("fma.rn.f32x2 %0, %1, %2, %0;" : "+l"(acc) : "l"(a), "l"(b));
}
__device__ __forceinline__ void cpasync16(uint32_t saddr, const void* g) {
    asm volatile("cp.async.cg.shared.global [%0], [%1], 16;" :: "r"(saddr), "l"(g));
}

struct Stage {
    float4 Lq; float Ls;
    float2 r0;
    float4 r1, r2, r3, r4, r5, r6;
};

__global__ void __launch_bounds__(THREADS, 6)
cv_kernel(const float* __restrict__ L, const float* __restrict__ R,
          float* __restrict__ out)
{
    extern __shared__ float smem[];
    float* sR = smem;                  // [2][CC][RW2]
    float* sL = smem + 2 * CC * RW2;   // [2][CC][LW]

    const int tid  = threadIdx.x;
    const int lane = tid & 31;
    const int w    = tid >> 5;               // 0..1
    const int h  = blockIdx.x;
    const int b  = blockIdx.y;
    const int xt = blockIdx.z;                // 0..1
    const int x0 = xt * XW;

    const int i0 = w * 24;                    // disparity base for this warp
    const int xb = lane * 4;                  // local x base
    const bool act = (lane < 30);

    const float* Lb = L + ((size_t)b * C_ * H_ + h) * W_;
    const float* Rb = R + ((size_t)b * C_ * H_ + h) * W_;

    // Zero R halo (tile idx [0,48) = x'<x0; only tile 0 leaves it unloaded).
    if (xt == 0) {
        for (int i = tid; i < 2 * CC * 48; i += THREADS) {
            int row = i / 48, k = i - row * 48;    // row in [0, 2*CC)
            sR[row * RW2 + k] = 0.0f;
        }
    }

    // --- division-free predicated loader: thread owns (row = tid>>2, c0 = tid&3),
    // quad columns c0+4k.  L: 31 quads (tile0) / 30 (tile1).  R: cols [rmin,42).
    const int lrw  = tid >> 2;                // 0..15
    const int c0   = tid & 3;
    const int lmax = (xt == 0) ? 30 : 29;     // last valid L quad col
    const int rmin = (xt == 0) ? 12 : 0;      // first valid R quad col
    const float* gLr = Lb + (size_t)lrw * HW_;     // + x0 + col*4 at use
    const float* gRr = Rb + (size_t)lrw * HW_;     // + x0-48 + col*4 at use
    const uint32_t sLr = (uint32_t)__cvta_generic_to_shared(sL)
                       + (uint32_t)(lrw * LW) * 4;
    const uint32_t sRr = (uint32_t)__cvta_generic_to_shared(sR)
                       + (uint32_t)(lrw * RW2) * 4;

    auto issue_load = [&](int buf, const float* gLc, const float* gRc) {
        const uint32_t dL = sLr + (uint32_t)buf * (CC * LW * 4);
        const uint32_t dR = sRr + (uint32_t)buf * (CC * RW2 * 4);
        #pragma unroll
        for (int k = 0; k < 8; k++) {
            int col = c0 + 4 * k;
            if (col <= lmax)
                cpasync16(dL + col * 16, gLc + x0 + col * 4);
        }
        #pragma unroll
        for (int k = 0; k < 11; k++) {
            int col = c0 + 4 * k;
            if (col >= rmin && col < 42)
                cpasync16(dR + col * 16, gRc + (x0 - 48) + col * 4);
        }
        asm volatile("cp.async.commit_group;");
    };

    // accE[j]: d=i0+2j,  x pairs (xb,xb+1),(xb+2,xb+3)
    // accO[j]: d=i0+2j+1, x pairs (xb+1,xb+2),(xb+3,xb+4)
    ull accE[12][2], accO[12][2];
    #pragma unroll
    for (int j = 0; j < 12; j++) {
        accE[j][0] = 0ull; accE[j][1] = 0ull;
        accO[j][0] = 0ull; accO[j][1] = 0ull;
    }

    issue_load(0, gLr, gRr);
    gLr += CC * HW_; gRr += CC * HW_;

    #pragma unroll 1
    for (int ch = 0; ch < NCH; ch++) {
        const int buf = ch & 1;
        if (ch + 1 < NCH) {
            issue_load((ch + 1) & 1, gLr, gRr);
            gLr += CC * HW_; gRr += CC * HW_;
            asm volatile("cp.async.wait_group 1;");
        } else {
            asm volatile("cp.async.wait_group 0;");
        }
        __syncthreads();

        if (act) {
            const float* lw = &sL[buf * (CC * LW)] + xb;
            const float* rw = &sR[buf * (CC * RW2)] + (xb - i0 + 24);
            Stage SA, SB;

            #define LDS_STAGE(S, cc) do {                                   \
                (S).Lq = *(const float4*)(lw + (cc) * LW);                  \
                (S).Ls = lw[(cc) * LW + 4];                                 \
                (S).r0 = *(const float2*)(rw + (cc) * RW2 + 2);             \
                (S).r1 = *(const float4*)(rw + (cc) * RW2 + 4);             \
                (S).r2 = *(const float4*)(rw + (cc) * RW2 + 8);             \
                (S).r3 = *(const float4*)(rw + (cc) * RW2 + 12);            \
                (S).r4 = *(const float4*)(rw + (cc) * RW2 + 16);            \
                (S).r5 = *(const float4*)(rw + (cc) * RW2 + 20);            \
                (S).r6 = *(const float4*)(rw + (cc) * RW2 + 24);            \
            } while (0)

            #define FMA_STAGE(S) do {                                       \
                ull Le0 = pk((S).Lq.x, (S).Lq.y);                           \
                ull Le1 = pk((S).Lq.z, (S).Lq.w);                           \
                ull Lo0 = pk((S).Lq.y, (S).Lq.z);                           \
                ull Lo1 = pk((S).Lq.w, (S).Ls);                             \
                ull P[14];                                                  \
                P[1]  = pk((S).r0.x, (S).r0.y);                             \
                P[2]  = pk((S).r1.x, (S).r1.y); P[3]  = pk((S).r1.z, (S).r1.w); \
                P[4]  = pk((S).r2.x, (S).r2.y); P[5]  = pk((S).r2.z, (S).r2.w); \
                P[6]  = pk((S).r3.x, (S).r3.y); P[7]  = pk((S).r3.z, (S).r3.w); \
                P[8]  = pk((S).r4.x, (S).r4.y); P[9]  = pk((S).r4.z, (S).r4.w); \
                P[10] = pk((S).r5.x, (S).r5.y); P[11] = pk((S).r5.z, (S).r5.w); \
                P[12] = pk((S).r6.x, (S).r6.y); P[13] = pk((S).r6.z, (S).r6.w); \
                _Pragma("unroll")                                           \
                for (int j = 0; j < 12; j++) {                              \
                    fma2(accE[j][0], Le0, P[12 - j]);                       \
                    fma2(accO[j][0], Lo0, P[12 - j]);                       \
                    fma2(accE[j][1], Le1, P[13 - j]);                       \
                    fma2(accO[j][1], Lo1, P[13 - j]);                       \
                }                                                           \
            } while (0)

            LDS_STAGE(SA, 0);
            #pragma unroll
            for (int cc = 0; cc < CC; cc += 2) {
                if (cc + 1 < CC) LDS_STAGE(SB, cc + 1);
                FMA_STAGE(SA);
                if (cc + 2 < CC) LDS_STAGE(SA, cc + 2);
                if (cc + 1 < CC) FMA_STAGE(SB);
            }
            #undef LDS_STAGE
            #undef FMA_STAGE
        }
        __syncthreads();
    }

    const float s = 1.0f / 128.0f;
    const bool edge4 = (xt == 0) || (lane < 29);   // x=xb+4 global valid
    if (act) {
        #pragma unroll
        for (int j = 0; j < 12; j++) {
            const int de = i0 + 2 * j;
            float a0, a1, a2, a3;
            upk(accE[j][0], a0, a1);
            upk(accE[j][1], a2, a3);
            float4 o;
            o.x = a0 * s; o.y = a1 * s; o.z = a2 * s; o.w = a3 * s;
            *(float4*)(out + (((size_t)b * V_ + de) * H_ + h) * W_ + x0 + xb) = o;

            float b0, b1, b2, b3;
            upk(accO[j][0], b0, b1);
            upk(accO[j][1], b2, b3);
            float* oo = out + (((size_t)b * V_ + de + 1) * H_ + h) * W_ + x0 + xb;
            oo[1] = b0 * s;
            oo[2] = b1 * s;
            oo[3] = b2 * s;
            if (edge4) oo[4] = b3 * s;   // tile0 lane29 -> x=120; tile1 lane29 skips x=240
        }
    } else if (lane == 30 && xt == 0) {
        // out[x=0, odd d]: never produced by the odd pipeline; 0 since x<d.
        #pragma unroll
        for (int j = 0; j < 12; j++) {
            const int d = i0 + 2 * j + 1;
            out[(((size_t)b * V_ + d) * H_ + h) * W_] = 0.0f;
        }
    }
}

extern "C" void kernel_launch(void* const* d_in, const int* in_sizes, int n_in,
                              void* d_out, int out_size)
{
    const float* L = (const float*)d_in[0];
    const float* R = (const float*)d_in[1];
    float* out = (float*)d_out;

    const int smem_bytes = (2 * CC * RW2 + 2 * CC * LW) * (int)sizeof(float); // 37376
    cudaFuncSetAttribute(cv_kernel, cudaFuncAttributeMaxDynamicSharedMemorySize,
                         smem_bytes);
    cv_kernel<<<dim3(H_, B_, 2), THREADS, smem_bytes>>>(L, R, out);
}